// round 1
// baseline (speedup 1.0000x reference)
#include <cuda_runtime.h>
#include <math.h>

#define NEG_SLOPE 0.2f

// Problem constants
#define BS 32
#define NA 512          // n_agents
#define ID 128          // input_dim
#define NH 8            // n_heads
#define HD 64           // hidden_dim

// h_prime scratch: [b][head][n][d] = 32*8*512*64 floats = 33.5 MB
__device__ float g_hp[BS * NH * NA * HD];

// ---------------------------------------------------------------------------
// Kernel A: hp = h @ W, written out in [b][head][n][d] layout.
// M = BS*NA = 16384 rows, K = 128, N = 512.
// Tile: 64 rows x 64 cols (one head per col-tile). 256 threads, 4x4 microtile.
// ---------------------------------------------------------------------------
#define A_PAD 132   // 128 + 4 floats padding (keeps 16B alignment: 132*4=528=33*16)
#define SMEM_A_BYTES ((64 * A_PAD + 128 * 64) * 4)

__global__ void __launch_bounds__(256, 3) gemm_hp_kernel(
    const float* __restrict__ h, const float* __restrict__ W)
{
    extern __shared__ float smemA[];
    float* As = smemA;              // [64][A_PAD]
    float* Bs = smemA + 64 * A_PAD; // [128][64]

    const int tid = threadIdx.x;
    const int tx = tid & 15;        // col group
    const int ty = tid >> 4;        // row group
    const int rowTile = blockIdx.y * 64;
    const int head = blockIdx.x;
    const int col0 = head * HD;

    // Load A tile: 64 rows x 128 K = 2048 float4, 8 per thread
    #pragma unroll
    for (int i = 0; i < 8; i++) {
        int idx = tid + i * 256;
        int r = idx >> 5;            // 32 float4 per row
        int kq = idx & 31;
        float4 v = *(const float4*)&h[(size_t)(rowTile + r) * ID + kq * 4];
        *(float4*)&As[r * A_PAD + kq * 4] = v;
    }
    // Load B tile: 128 k x 64 cols = 2048 float4, 8 per thread
    #pragma unroll
    for (int i = 0; i < 8; i++) {
        int idx = tid + i * 256;
        int k = idx >> 4;            // 16 float4 per k-row
        int cq = idx & 15;
        float4 v = *(const float4*)&W[(size_t)k * 512 + col0 + cq * 4];
        *(float4*)&Bs[k * 64 + cq * 4] = v;
    }
    __syncthreads();

    float acc[4][4];
    #pragma unroll
    for (int i = 0; i < 4; i++)
        #pragma unroll
        for (int j = 0; j < 4; j++) acc[i][j] = 0.f;

    #pragma unroll 8
    for (int k = 0; k < ID; k++) {
        float a0 = As[(ty * 4 + 0) * A_PAD + k];
        float a1 = As[(ty * 4 + 1) * A_PAD + k];
        float a2 = As[(ty * 4 + 2) * A_PAD + k];
        float a3 = As[(ty * 4 + 3) * A_PAD + k];
        float4 b = *(float4*)&Bs[k * 64 + tx * 4];
        acc[0][0] += a0 * b.x; acc[0][1] += a0 * b.y; acc[0][2] += a0 * b.z; acc[0][3] += a0 * b.w;
        acc[1][0] += a1 * b.x; acc[1][1] += a1 * b.y; acc[1][2] += a1 * b.z; acc[1][3] += a1 * b.w;
        acc[2][0] += a2 * b.x; acc[2][1] += a2 * b.y; acc[2][2] += a2 * b.z; acc[2][3] += a2 * b.w;
        acc[3][0] += a3 * b.x; acc[3][1] += a3 * b.y; acc[3][2] += a3 * b.z; acc[3][3] += a3 * b.w;
    }

    // Epilogue: write to g_hp[b][head][n][d]
    #pragma unroll
    for (int i = 0; i < 4; i++) {
        int row = rowTile + ty * 4 + i;        // global M index
        int b = row >> 9;                      // /512
        int n = row & 511;
        size_t base = (((size_t)b * NH + head) * NA + n) * HD + tx * 4;
        float4 v;
        v.x = acc[i][0]; v.y = acc[i][1]; v.z = acc[i][2]; v.w = acc[i][3];
        *(float4*)&g_hp[base] = v;
    }
}

// ---------------------------------------------------------------------------
// Kernel B: per (b,h) CTA. Loads hp tile [512][64] to SMEM, computes
// e_src/e_dst, then 16 passes of (weight-gen -> unnormalized attention GEMM),
// normalizing by 1/sum at the epilogue, then ELU.
// ---------------------------------------------------------------------------
#define SMEM_B_FLOATS (NA * HD /*hp*/ + 8 * NA * 4 /*w*/ + NA /*e_src*/ + NA /*e_dst*/ + 128 /*a*/)
#define SMEM_B_BYTES (SMEM_B_FLOATS * 4)

__device__ __forceinline__ float elu1(float x) {
    return x > 0.f ? x : expm1f(x);
}

__global__ void __launch_bounds__(256, 1) attn_kernel(
    const float* __restrict__ att_a, float* __restrict__ out)
{
    extern __shared__ float smem[];
    float* hp_s  = smem;                          // [512][64]
    float* w_s   = hp_s + NA * HD;                // [8 warps][512 m][4 rows]
    float* e_src = w_s + 8 * NA * 4;              // [512]
    float* e_dst = e_src + NA;                    // [512]
    float* a_s   = e_dst + NA;                    // [128]

    const int bh = blockIdx.x;
    const int head = bh & 7;
    const int tid = threadIdx.x;
    const int warp = tid >> 5;
    const int lane = tid & 31;

    // Load hp tile (contiguous 128KB)
    const float* hp_g = g_hp + (size_t)bh * NA * HD;
    for (int i = tid; i < NA * HD / 4; i += 256)
        *(float4*)&hp_s[i * 4] = *(const float4*)&hp_g[i * 4];
    if (tid < 128) a_s[tid] = att_a[head * 128 + tid];
    __syncthreads();

    // e_src/e_dst: one warp per 64 consecutive rows, warp-cooperative dots
    for (int r = warp * 64; r < warp * 64 + 64; r++) {
        float hp0 = hp_s[r * HD + lane];
        float hp1 = hp_s[r * HD + 32 + lane];
        float es = hp0 * a_s[lane]       + hp1 * a_s[32 + lane];
        float ed = hp0 * a_s[64 + lane]  + hp1 * a_s[96 + lane];
        #pragma unroll
        for (int o = 16; o; o >>= 1) {
            es += __shfl_xor_sync(0xFFFFFFFFu, es, o);
            ed += __shfl_xor_sync(0xFFFFFFFFu, ed, o);
        }
        if (lane == 0) { e_src[r] = es; e_dst[r] = ed; }
    }
    __syncthreads();

    float* w_w = w_s + warp * NA * 4;
    const int quad = lane & 15;          // d-quad index (0..15)
    const int rhalf = (lane >> 4) * 2;   // rows {0,1} or {2,3} of the block

    for (int pass = 0; pass < 16; pass++) {
        const int base = pass * 32 + warp * 4;  // 4 rows per warp per pass

        // ---- weight generation (per-warp private w_w) ----
        float inv[4];
        #pragma unroll
        for (int r = 0; r < 4; r++) {
            float es = e_src[base + r];
            float sum = 0.f;
            #pragma unroll
            for (int j = 0; j < 16; j++) {
                int m = lane + 32 * j;
                float v = es + e_dst[m];
                v = v >= 0.f ? v : NEG_SLOPE * v;
                float wv = __expf(v);
                sum += wv;
                w_w[m * 4 + r] = wv;
            }
            #pragma unroll
            for (int o = 16; o; o >>= 1)
                sum += __shfl_xor_sync(0xFFFFFFFFu, sum, o);
            inv[r] = 1.f / sum;
        }
        __syncwarp();

        // ---- GEMM: acc[2 rows][4 d] over m ----
        float4 a0 = make_float4(0.f, 0.f, 0.f, 0.f);
        float4 a1 = make_float4(0.f, 0.f, 0.f, 0.f);
        #pragma unroll 8
        for (int m = 0; m < NA; m++) {
            float4 hp4 = *(float4*)&hp_s[m * HD + quad * 4];
            float2 w2  = *(float2*)&w_w[m * 4 + rhalf];
            a0.x += w2.x * hp4.x; a0.y += w2.x * hp4.y;
            a0.z += w2.x * hp4.z; a0.w += w2.x * hp4.w;
            a1.x += w2.y * hp4.x; a1.y += w2.y * hp4.y;
            a1.z += w2.y * hp4.z; a1.w += w2.y * hp4.w;
        }

        // ---- epilogue: normalize, ELU, store ----
        float i0 = inv[rhalf], i1 = inv[rhalf + 1];
        int row0 = base + rhalf;
        size_t obase = ((size_t)bh * NA + row0) * HD + quad * 4;
        float4 o0, o1;
        o0.x = elu1(a0.x * i0); o0.y = elu1(a0.y * i0);
        o0.z = elu1(a0.z * i0); o0.w = elu1(a0.w * i0);
        o1.x = elu1(a1.x * i1); o1.y = elu1(a1.y * i1);
        o1.z = elu1(a1.z * i1); o1.w = elu1(a1.w * i1);
        *(float4*)&out[obase] = o0;
        *(float4*)&out[obase + HD] = o1;
        __syncwarp();   // w_w reuse next pass
    }
}

// ---------------------------------------------------------------------------
extern "C" void kernel_launch(void* const* d_in, const int* in_sizes, int n_in,
                              void* d_out, int out_size)
{
    const float* h     = (const float*)d_in[0];
    const float* W     = (const float*)d_in[1];
    const float* att_a = (const float*)d_in[2];
    float* out = (float*)d_out;

    cudaFuncSetAttribute(gemm_hp_kernel,
        cudaFuncAttributeMaxDynamicSharedMemorySize, SMEM_A_BYTES);
    cudaFuncSetAttribute(attn_kernel,
        cudaFuncAttributeMaxDynamicSharedMemorySize, SMEM_B_BYTES);

    gemm_hp_kernel<<<dim3(NH, (BS * NA) / 64), 256, SMEM_A_BYTES>>>(h, W);
    attn_kernel<<<BS * NH, 256, SMEM_B_BYTES>>>(att_a, out);
}

// round 2
// speedup vs baseline: 1.2953x; 1.2953x over previous
#include <cuda_runtime.h>
#include <math.h>

#define NEG_SLOPE 0.2f

// Problem constants
#define BS 32
#define NA 512          // n_agents
#define ID 128          // input_dim
#define NH 8            // n_heads
#define HD 64           // hidden_dim

// h_prime scratch: [b][head][n][d] = 32*8*512*64 floats = 33.5 MB
__device__ float g_hp[BS * NH * NA * HD];

// ---------------------------------------------------------------------------
// Kernel A: hp = h @ W, written out in [b][head][n][d] layout. (unchanged)
// ---------------------------------------------------------------------------
#define A_PAD 132
#define SMEM_A_BYTES ((64 * A_PAD + 128 * 64) * 4)

__global__ void __launch_bounds__(256, 3) gemm_hp_kernel(
    const float* __restrict__ h, const float* __restrict__ W)
{
    extern __shared__ float smemA[];
    float* As = smemA;              // [64][A_PAD]
    float* Bs = smemA + 64 * A_PAD; // [128][64]

    const int tid = threadIdx.x;
    const int tx = tid & 15;
    const int ty = tid >> 4;
    const int rowTile = blockIdx.y * 64;
    const int head = blockIdx.x;
    const int col0 = head * HD;

    #pragma unroll
    for (int i = 0; i < 8; i++) {
        int idx = tid + i * 256;
        int r = idx >> 5;
        int kq = idx & 31;
        float4 v = *(const float4*)&h[(size_t)(rowTile + r) * ID + kq * 4];
        *(float4*)&As[r * A_PAD + kq * 4] = v;
    }
    #pragma unroll
    for (int i = 0; i < 8; i++) {
        int idx = tid + i * 256;
        int k = idx >> 4;
        int cq = idx & 15;
        float4 v = *(const float4*)&W[(size_t)k * 512 + col0 + cq * 4];
        *(float4*)&Bs[k * 64 + cq * 4] = v;
    }
    __syncthreads();

    float acc[4][4];
    #pragma unroll
    for (int i = 0; i < 4; i++)
        #pragma unroll
        for (int j = 0; j < 4; j++) acc[i][j] = 0.f;

    #pragma unroll 8
    for (int k = 0; k < ID; k++) {
        float a0 = As[(ty * 4 + 0) * A_PAD + k];
        float a1 = As[(ty * 4 + 1) * A_PAD + k];
        float a2 = As[(ty * 4 + 2) * A_PAD + k];
        float a3 = As[(ty * 4 + 3) * A_PAD + k];
        float4 b = *(float4*)&Bs[k * 64 + tx * 4];
        acc[0][0] += a0 * b.x; acc[0][1] += a0 * b.y; acc[0][2] += a0 * b.z; acc[0][3] += a0 * b.w;
        acc[1][0] += a1 * b.x; acc[1][1] += a1 * b.y; acc[1][2] += a1 * b.z; acc[1][3] += a1 * b.w;
        acc[2][0] += a2 * b.x; acc[2][1] += a2 * b.y; acc[2][2] += a2 * b.z; acc[2][3] += a2 * b.w;
        acc[3][0] += a3 * b.x; acc[3][1] += a3 * b.y; acc[3][2] += a3 * b.z; acc[3][3] += a3 * b.w;
    }

    #pragma unroll
    for (int i = 0; i < 4; i++) {
        int row = rowTile + ty * 4 + i;
        int b = row >> 9;
        int n = row & 511;
        size_t base = (((size_t)b * NH + head) * NA + n) * HD + tx * 4;
        float4 v;
        v.x = acc[i][0]; v.y = acc[i][1]; v.z = acc[i][2]; v.w = acc[i][3];
        *(float4*)&g_hp[base] = v;
    }
}

// ---------------------------------------------------------------------------
// Kernel B: per (b,h) CTA. 8 warps, each warp owns 64 rows (8 passes x 8 rows).
// Per pass: weight-gen into per-warp smem chunk [8 rows][256 m], then GEMM
// with 8-row x 4-d register blocking (32 FFMA per 2 LDS-ish), m split over
// lane halves, combined by shfl at the epilogue. Normalization folded into
// the epilogue (softmax is linear in the normalizer).
// ---------------------------------------------------------------------------
#define W_CHUNK 256
#define SMEM_B_FLOATS (NA * HD /*hp*/ + 8 * 8 * W_CHUNK /*w*/ + NA + NA + 128)
#define SMEM_B_BYTES (SMEM_B_FLOATS * 4)

__device__ __forceinline__ float elu1(float x) {
    return x > 0.f ? x : expm1f(x);
}

__global__ void __launch_bounds__(256, 1) attn_kernel(
    const float* __restrict__ att_a, float* __restrict__ out)
{
    extern __shared__ float smem[];
    float* hp_s  = smem;                          // [512][64]
    float* w_s   = hp_s + NA * HD;                // [8 warps][8 r][256 m]
    float* e_src = w_s + 8 * 8 * W_CHUNK;         // [512]
    float* e_dst = e_src + NA;                    // [512]
    float* a_s   = e_dst + NA;                    // [128]

    const int bh = blockIdx.x;
    const int head = bh & 7;
    const int tid = threadIdx.x;
    const int warp = tid >> 5;
    const int lane = tid & 31;
    const int quad = lane & 15;          // d-quad (0..15)
    const int mhalf = lane >> 4;         // m parity (0/1)

    // Load hp tile (contiguous 128KB)
    const float* hp_g = g_hp + (size_t)bh * NA * HD;
    for (int i = tid; i < NA * HD / 4; i += 256)
        *(float4*)&hp_s[i * 4] = *(const float4*)&hp_g[i * 4];
    if (tid < 128) a_s[tid] = att_a[head * 128 + tid];
    __syncthreads();

    // e_src/e_dst: one warp per 64 consecutive rows
    for (int r = warp * 64; r < warp * 64 + 64; r++) {
        float hp0 = hp_s[r * HD + lane];
        float hp1 = hp_s[r * HD + 32 + lane];
        float es = hp0 * a_s[lane]       + hp1 * a_s[32 + lane];
        float ed = hp0 * a_s[64 + lane]  + hp1 * a_s[96 + lane];
        #pragma unroll
        for (int o = 16; o; o >>= 1) {
            es += __shfl_xor_sync(0xFFFFFFFFu, es, o);
            ed += __shfl_xor_sync(0xFFFFFFFFu, ed, o);
        }
        if (lane == 0) { e_src[r] = es; e_dst[r] = ed; }
    }
    __syncthreads();

    float* w_w = w_s + warp * (8 * W_CHUNK);   // private per warp
    const int row0 = warp * 64;

    for (int pass = 0; pass < 8; pass++) {
        const int base = row0 + pass * 8;

        float es[8];
        #pragma unroll
        for (int r = 0; r < 8; r++) es[r] = e_src[base + r];

        float sum[8];
        float acc[8][4];
        #pragma unroll
        for (int r = 0; r < 8; r++) {
            sum[r] = 0.f;
            acc[r][0] = acc[r][1] = acc[r][2] = acc[r][3] = 0.f;
        }

        #pragma unroll
        for (int c = 0; c < 2; c++) {
            const int mbase = c * W_CHUNK;

            // ---- weight generation for this m-chunk ----
            #pragma unroll
            for (int j = 0; j < 8; j++) {
                int ml = j * 32 + lane;
                float ed = e_dst[mbase + ml];
                #pragma unroll
                for (int r = 0; r < 8; r++) {
                    float v = es[r] + ed;
                    v = v >= 0.f ? v : NEG_SLOPE * v;
                    float wv = __expf(v);
                    sum[r] += wv;
                    w_w[r * W_CHUNK + ml] = wv;   // lane-consecutive: conflict-free
                }
            }
            __syncwarp();

            // ---- GEMM over this chunk: 8 rows x 4 d per lane ----
            #pragma unroll 4
            for (int j2 = 0; j2 < W_CHUNK / 2; j2++) {
                int ml = j2 * 2 + mhalf;
                float4 hp4 = *(float4*)&hp_s[(mbase + ml) * HD + quad * 4];
                #pragma unroll
                for (int r = 0; r < 8; r++) {
                    float wv = w_w[r * W_CHUNK + ml];  // 16-lane broadcast
                    acc[r][0] += wv * hp4.x;
                    acc[r][1] += wv * hp4.y;
                    acc[r][2] += wv * hp4.z;
                    acc[r][3] += wv * hp4.w;
                }
            }
            __syncwarp();
        }

        // ---- reduce row sums across the warp ----
        #pragma unroll
        for (int r = 0; r < 8; r++) {
            #pragma unroll
            for (int o = 16; o; o >>= 1)
                sum[r] += __shfl_xor_sync(0xFFFFFFFFu, sum[r], o);
        }

        // ---- combine the two m-halves ----
        #pragma unroll
        for (int r = 0; r < 8; r++) {
            #pragma unroll
            for (int k = 0; k < 4; k++)
                acc[r][k] += __shfl_xor_sync(0xFFFFFFFFu, acc[r][k], 16);
        }

        // ---- epilogue: normalize, ELU, store (4 rows per lane) ----
        #pragma unroll
        for (int rr = 0; rr < 4; rr++) {
            int r = mhalf * 4 + rr;
            float iv = 1.f / sum[r];
            float4 o;
            o.x = elu1(acc[r][0] * iv);
            o.y = elu1(acc[r][1] * iv);
            o.z = elu1(acc[r][2] * iv);
            o.w = elu1(acc[r][3] * iv);
            size_t obase = ((size_t)bh * NA + base + r) * HD + quad * 4;
            *(float4*)&out[obase] = o;
        }
    }
}

// ---------------------------------------------------------------------------
extern "C" void kernel_launch(void* const* d_in, const int* in_sizes, int n_in,
                              void* d_out, int out_size)
{
    const float* h     = (const float*)d_in[0];
    const float* W     = (const float*)d_in[1];
    const float* att_a = (const float*)d_in[2];
    float* out = (float*)d_out;

    cudaFuncSetAttribute(gemm_hp_kernel,
        cudaFuncAttributeMaxDynamicSharedMemorySize, SMEM_A_BYTES);
    cudaFuncSetAttribute(attn_kernel,
        cudaFuncAttributeMaxDynamicSharedMemorySize, SMEM_B_BYTES);

    gemm_hp_kernel<<<dim3(NH, (BS * NA) / 64), 256, SMEM_A_BYTES>>>(h, W);
    attn_kernel<<<BS * NH, 256, SMEM_B_BYTES>>>(att_a, out);
}

// round 3
// speedup vs baseline: 1.3032x; 1.0061x over previous
#include <cuda_runtime.h>
#include <math.h>

#define NEG_SLOPE 0.2f

// Problem constants
#define BS 32
#define NA 512          // n_agents
#define ID 128          // input_dim
#define NH 8            // n_heads
#define HD 64           // hidden_dim

typedef unsigned long long ull;

// h_prime scratch: [b][head][n][d] = 32*8*512*64 floats = 33.5 MB
__device__ float g_hp[BS * NH * NA * HD];

// ---- f32x2 packed helpers -------------------------------------------------
__device__ __forceinline__ ull pack2(float lo, float hi) {
    ull r; asm("mov.b64 %0, {%1, %2};" : "=l"(r) : "f"(lo), "f"(hi)); return r;
}
__device__ __forceinline__ void unpack2(ull v, float& lo, float& hi) {
    asm("mov.b64 {%0, %1}, %2;" : "=f"(lo), "=f"(hi) : "l"(v));
}
__device__ __forceinline__ void ffma2(ull& d, ull a, ull b) {
    asm("fma.rn.f32x2 %0, %1, %2, %0;" : "+l"(d) : "l"(a), "l"(b));
}

// ---------------------------------------------------------------------------
// Kernel A: hp = h @ W  ->  g_hp[b][head][n][d].  FFMA2 inner loop.
// ---------------------------------------------------------------------------
#define A_PAD 132
#define SMEM_A_BYTES ((64 * A_PAD + 128 * 64) * 4)

__global__ void __launch_bounds__(256, 3) gemm_hp_kernel(
    const float* __restrict__ h, const float* __restrict__ W)
{
    extern __shared__ float smemA[];
    float* As = smemA;              // [64][A_PAD]
    float* Bs = smemA + 64 * A_PAD; // [128][64]

    const int tid = threadIdx.x;
    const int tx = tid & 15;
    const int ty = tid >> 4;
    const int rowTile = blockIdx.y * 64;
    const int head = blockIdx.x;
    const int col0 = head * HD;

    #pragma unroll
    for (int i = 0; i < 8; i++) {
        int idx = tid + i * 256;
        int r = idx >> 5;
        int kq = idx & 31;
        float4 v = *(const float4*)&h[(size_t)(rowTile + r) * ID + kq * 4];
        *(float4*)&As[r * A_PAD + kq * 4] = v;
    }
    #pragma unroll
    for (int i = 0; i < 8; i++) {
        int idx = tid + i * 256;
        int k = idx >> 4;
        int cq = idx & 15;
        float4 v = *(const float4*)&W[(size_t)k * 512 + col0 + cq * 4];
        *(float4*)&Bs[k * 64 + cq * 4] = v;
    }
    __syncthreads();

    ull acc2[4][2];
    #pragma unroll
    for (int i = 0; i < 4; i++) { acc2[i][0] = 0ull; acc2[i][1] = 0ull; }

    #pragma unroll 4
    for (int k4 = 0; k4 < 32; k4++) {
        float a_[4][4];
        #pragma unroll
        for (int i = 0; i < 4; i++)
            *(float4*)a_[i] = *(const float4*)&As[(ty * 4 + i) * A_PAD + k4 * 4];
        #pragma unroll
        for (int kk = 0; kk < 4; kk++) {
            const float* bp = &Bs[(k4 * 4 + kk) * 64 + tx * 4];
            ull b01 = *(const ull*)bp;
            ull b23 = *(const ull*)(bp + 2);
            #pragma unroll
            for (int i = 0; i < 4; i++) {
                ull ad = pack2(a_[i][kk], a_[i][kk]);
                ffma2(acc2[i][0], ad, b01);
                ffma2(acc2[i][1], ad, b23);
            }
        }
    }

    #pragma unroll
    for (int i = 0; i < 4; i++) {
        int row = rowTile + ty * 4 + i;
        int b = row >> 9;
        int n = row & 511;
        size_t base = (((size_t)b * NH + head) * NA + n) * HD + tx * 4;
        float4 v;
        unpack2(acc2[i][0], v.x, v.y);
        unpack2(acc2[i][1], v.z, v.w);
        *(float4*)&g_hp[base] = v;
    }
}

// ---------------------------------------------------------------------------
// Kernel B: 4 CTAs per (b,h), each does 128 n-rows over the full 512-m scan.
// hp tile stored in SMEM with a 16B-chunk XOR swizzle (c ^= m&3) so the
// 8d x 4m lane tiling reads conflict-free. Weights [m][8r] in per-warp SMEM
// chunks; GEMM uses fma.rn.f32x2 with 8 rows x 8 d (4 f32x2 pairs) per lane.
// ---------------------------------------------------------------------------
#define W_CHUNK 256
#define SMEM_B_FLOATS (NA * HD + 8 * W_CHUNK * 8 + NA + NA + 128)
#define SMEM_B_BYTES (SMEM_B_FLOATS * 4)

__device__ __forceinline__ float elu1(float x) {
    return x > 0.f ? x : expm1f(x);
}

__global__ void __launch_bounds__(256) attn_kernel(
    const float* __restrict__ att_a, float* __restrict__ out)
{
    extern __shared__ float smem[];
    float* hp_s  = smem;                          // [512][64] swizzled
    float* w_s   = hp_s + NA * HD;                // [8 warps][256 m][8 r]
    float* e_src = w_s + 8 * W_CHUNK * 8;         // [512]
    float* e_dst = e_src + NA;                    // [512]
    float* a_s   = e_dst + NA;                    // [128]

    const int bx = blockIdx.x;
    const int bh = bx >> 2;
    const int head = bh & 7;
    const int nbase = (bx & 3) * 128;
    const int tid = threadIdx.x;
    const int warp = tid >> 5;
    const int lane = tid & 31;
    const int dgrp = lane & 7;       // d-block: d = dgrp*8 .. +8
    const int mq = lane >> 3;        // m residue (0..3)

    // Load hp tile, applying chunk swizzle: chunk c of row m -> c ^ (m&3)
    const float* hp_g = g_hp + (size_t)bh * NA * HD;
    for (int f = tid; f < NA * HD / 4; f += 256) {
        int m = f >> 4;
        int c = f & 15;
        float4 v = *(const float4*)&hp_g[(size_t)f * 4];
        *(float4*)&hp_s[m * 64 + ((c ^ (m & 3)) << 2)] = v;
    }
    if (tid < 128) a_s[tid] = att_a[head * 128 + tid];
    __syncthreads();

    // e_src / e_dst for all 512 rows (one warp per 64 rows)
    for (int r = warp * 64; r < warp * 64 + 64; r++) {
        int c0 = lane >> 2;
        int w0 = (((c0) ^ (r & 3)) << 2) + (lane & 3);
        int w1 = (((c0 + 8) ^ (r & 3)) << 2) + (lane & 3);
        float hp0 = hp_s[r * 64 + w0];
        float hp1 = hp_s[r * 64 + w1];
        float es = hp0 * a_s[lane]      + hp1 * a_s[32 + lane];
        float ed = hp0 * a_s[64 + lane] + hp1 * a_s[96 + lane];
        #pragma unroll
        for (int o = 16; o; o >>= 1) {
            es += __shfl_xor_sync(0xFFFFFFFFu, es, o);
            ed += __shfl_xor_sync(0xFFFFFFFFu, ed, o);
        }
        if (lane == 0) { e_src[r] = es; e_dst[r] = ed; }
    }
    __syncthreads();

    float* w_w = w_s + warp * (W_CHUNK * 8);  // per-warp private
    const int row0 = nbase + warp * 16;
    // Loop-invariant swizzled chunk offsets for this lane (m&3 == mq always)
    const int coff0 = ((2 * dgrp) ^ mq) << 2;
    const int coff1 = ((2 * dgrp + 1) ^ mq) << 2;

    for (int pass = 0; pass < 2; pass++) {
        const int base = row0 + pass * 8;

        float es[8];
        #pragma unroll
        for (int r = 0; r < 8; r++) es[r] = e_src[base + r];

        ull acc[8][4];
        float sum[8];
        #pragma unroll
        for (int r = 0; r < 8; r++) {
            sum[r] = 0.f;
            acc[r][0] = acc[r][1] = acc[r][2] = acc[r][3] = 0ull;
        }

        #pragma unroll
        for (int cch = 0; cch < 2; cch++) {
            const int mbase = cch * W_CHUNK;

            // ---- weight generation: lane owns m = mbase + lane + 32g ----
            #pragma unroll
            for (int g = 0; g < 8; g++) {
                int mm = g * 32 + lane;
                float ed = e_dst[mbase + mm];
                float wr[8];
                #pragma unroll
                for (int r = 0; r < 8; r++) {
                    float v = es[r] + ed;
                    v = v >= 0.f ? v : NEG_SLOPE * v;
                    float wv = __expf(v);
                    sum[r] += wv;
                    wr[r] = wv;
                }
                *(float4*)&w_w[mm * 8]     = make_float4(wr[0], wr[1], wr[2], wr[3]);
                *(float4*)&w_w[mm * 8 + 4] = make_float4(wr[4], wr[5], wr[6], wr[7]);
            }
            __syncwarp();

            // ---- GEMM over this chunk: lane does m = mbase+mq, +4, ... ----
            const float* hpb = hp_s + (size_t)(mbase + mq) * 64;
            const float* wwb = w_w + mq * 8;
            #pragma unroll 2
            for (int j = 0; j < W_CHUNK / 4; j++) {
                const float* hq = hpb + j * 256;
                ull h0 = *(const ull*)&hq[coff0];       // d0,d1
                ull h1 = *(const ull*)&hq[coff0 + 2];   // d2,d3
                ull h2 = *(const ull*)&hq[coff1];       // d4,d5
                ull h3 = *(const ull*)&hq[coff1 + 2];   // d6,d7
                float4 wa = *(const float4*)&wwb[j * 32];
                float4 wb = *(const float4*)&wwb[j * 32 + 4];
                ull wp;
                wp = pack2(wa.x, wa.x);
                ffma2(acc[0][0], h0, wp); ffma2(acc[0][1], h1, wp);
                ffma2(acc[0][2], h2, wp); ffma2(acc[0][3], h3, wp);
                wp = pack2(wa.y, wa.y);
                ffma2(acc[1][0], h0, wp); ffma2(acc[1][1], h1, wp);
                ffma2(acc[1][2], h2, wp); ffma2(acc[1][3], h3, wp);
                wp = pack2(wa.z, wa.z);
                ffma2(acc[2][0], h0, wp); ffma2(acc[2][1], h1, wp);
                ffma2(acc[2][2], h2, wp); ffma2(acc[2][3], h3, wp);
                wp = pack2(wa.w, wa.w);
                ffma2(acc[3][0], h0, wp); ffma2(acc[3][1], h1, wp);
                ffma2(acc[3][2], h2, wp); ffma2(acc[3][3], h3, wp);
                wp = pack2(wb.x, wb.x);
                ffma2(acc[4][0], h0, wp); ffma2(acc[4][1], h1, wp);
                ffma2(acc[4][2], h2, wp); ffma2(acc[4][3], h3, wp);
                wp = pack2(wb.y, wb.y);
                ffma2(acc[5][0], h0, wp); ffma2(acc[5][1], h1, wp);
                ffma2(acc[5][2], h2, wp); ffma2(acc[5][3], h3, wp);
                wp = pack2(wb.z, wb.z);
                ffma2(acc[6][0], h0, wp); ffma2(acc[6][1], h1, wp);
                ffma2(acc[6][2], h2, wp); ffma2(acc[6][3], h3, wp);
                wp = pack2(wb.w, wb.w);
                ffma2(acc[7][0], h0, wp); ffma2(acc[7][1], h1, wp);
                ffma2(acc[7][2], h2, wp); ffma2(acc[7][3], h3, wp);
            }
            __syncwarp();
        }

        // ---- reduce row sums across the whole warp ----
        #pragma unroll
        for (int r = 0; r < 8; r++) {
            #pragma unroll
            for (int o = 16; o; o >>= 1)
                sum[r] += __shfl_xor_sync(0xFFFFFFFFu, sum[r], o);
        }

        // ---- combine the 4 m-residue partials (lanes differing in bits 3,4) ----
        #pragma unroll
        for (int r = 0; r < 8; r++) {
            #pragma unroll
            for (int p = 0; p < 4; p++) {
                ull v = acc[r][p];
                ull v8  = __shfl_xor_sync(0xFFFFFFFFu, v, 8);
                float a, b, c, d;
                unpack2(v, a, b); unpack2(v8, c, d);
                a += c; b += d;
                v = pack2(a, b);
                ull v16 = __shfl_xor_sync(0xFFFFFFFFu, v, 16);
                unpack2(v, a, b); unpack2(v16, c, d);
                a += c; b += d;
                acc[r][p] = pack2(a, b);
            }
        }

        // ---- epilogue: each lane writes rows r = mq*2, mq*2+1 (its dgrp slice) ----
        #pragma unroll
        for (int rr = 0; rr < 2; rr++) {
            int r = mq * 2 + rr;
            float iv = 1.f / sum[r];
            float f[8];
            unpack2(acc[r][0], f[0], f[1]);
            unpack2(acc[r][1], f[2], f[3]);
            unpack2(acc[r][2], f[4], f[5]);
            unpack2(acc[r][3], f[6], f[7]);
            float4 o0, o1;
            o0.x = elu1(f[0] * iv); o0.y = elu1(f[1] * iv);
            o0.z = elu1(f[2] * iv); o0.w = elu1(f[3] * iv);
            o1.x = elu1(f[4] * iv); o1.y = elu1(f[5] * iv);
            o1.z = elu1(f[6] * iv); o1.w = elu1(f[7] * iv);
            size_t obase = ((size_t)bh * NA + base + r) * HD + dgrp * 8;
            *(float4*)&out[obase] = o0;
            *(float4*)&out[obase + 4] = o1;
        }
    }
}

// ---------------------------------------------------------------------------
extern "C" void kernel_launch(void* const* d_in, const int* in_sizes, int n_in,
                              void* d_out, int out_size)
{
    const float* h     = (const float*)d_in[0];
    const float* W     = (const float*)d_in[1];
    const float* att_a = (const float*)d_in[2];
    float* out = (float*)d_out;

    cudaFuncSetAttribute(gemm_hp_kernel,
        cudaFuncAttributeMaxDynamicSharedMemorySize, SMEM_A_BYTES);
    cudaFuncSetAttribute(attn_kernel,
        cudaFuncAttributeMaxDynamicSharedMemorySize, SMEM_B_BYTES);

    gemm_hp_kernel<<<dim3(NH, (BS * NA) / 64), 256, SMEM_A_BYTES>>>(h, W);
    attn_kernel<<<BS * NH * 4, 256, SMEM_B_BYTES>>>(att_a, out);
}

// round 5
// speedup vs baseline: 3.2573x; 2.4995x over previous
#include <cuda_runtime.h>
#include <math.h>
#include <stdint.h>

#define NEG_SLOPE 0.2f
#define LOG2E 1.4426950408889634f

// Problem constants
#define BS 32
#define NA 512          // n_agents
#define ID 128          // input_dim
#define NH 8            // n_heads
#define HD 64           // hidden_dim

typedef unsigned long long ull;

// h_prime^T scratch: [b][head][d][m] = 32*8*64*512 floats = 33.5 MB
__device__ float g_hpT[BS * NH * HD * NA];

// ---------------------------------------------------------------------------
// helpers
// ---------------------------------------------------------------------------
__device__ __forceinline__ float to_tf32(float x) {
    uint32_t u;
    asm("cvt.rn.tf32.f32 %0, %1;" : "=r"(u) : "f"(x));
    return __uint_as_float(u);
}
__device__ __forceinline__ float ex2(float x) {
    float r;
    asm("ex2.approx.f32 %0, %1;" : "=f"(r) : "f"(x));
    return r;
}
__device__ __forceinline__ ull pack2(float lo, float hi) {
    ull r; asm("mov.b64 %0, {%1, %2};" : "=l"(r) : "f"(lo), "f"(hi)); return r;
}
__device__ __forceinline__ void unpack2(ull v, float& lo, float& hi) {
    asm("mov.b64 {%0, %1}, %2;" : "=f"(lo), "=f"(hi) : "l"(v));
}
__device__ __forceinline__ void ffma2(ull& d, ull a, ull b) {
    asm("fma.rn.f32x2 %0, %1, %2, %0;" : "+l"(d) : "l"(a), "l"(b));
}
__device__ __forceinline__ void mma_tf32(float d[4], float a0, float a1,
                                         float a2, float a3, float b0, float b1) {
    asm volatile(
        "mma.sync.aligned.m16n8k8.row.col.f32.tf32.tf32.f32 "
        "{%0,%1,%2,%3}, {%4,%5,%6,%7}, {%8,%9}, {%0,%1,%2,%3};"
        : "+f"(d[0]), "+f"(d[1]), "+f"(d[2]), "+f"(d[3])
        : "r"(__float_as_uint(a0)), "r"(__float_as_uint(a1)),
          "r"(__float_as_uint(a2)), "r"(__float_as_uint(a3)),
          "r"(__float_as_uint(b0)), "r"(__float_as_uint(b1)));
}

// ---------------------------------------------------------------------------
// Kernel A: hp = h @ W -> g_hpT[b][head][d][m]  (fp32 FFMA2, as in R3/R4)
// ---------------------------------------------------------------------------
#define A_PAD 132
#define SMEM_A_BYTES ((64 * A_PAD + 128 * 64) * 4)
#define T_PAD 68

__global__ void __launch_bounds__(256, 3) gemm_hp_kernel(
    const float* __restrict__ h, const float* __restrict__ W)
{
    extern __shared__ float smemA[];
    float* As = smemA;              // [64][A_PAD]
    float* Bs = smemA + 64 * A_PAD; // [128][64]

    const int tid = threadIdx.x;
    const int tx = tid & 15;
    const int ty = tid >> 4;
    const int rowTile = blockIdx.y * 64;
    const int head = blockIdx.x;
    const int col0 = head * HD;

    #pragma unroll
    for (int i = 0; i < 8; i++) {
        int idx = tid + i * 256;
        int r = idx >> 5;
        int kq = idx & 31;
        float4 v = *(const float4*)&h[(size_t)(rowTile + r) * ID + kq * 4];
        *(float4*)&As[r * A_PAD + kq * 4] = v;
    }
    #pragma unroll
    for (int i = 0; i < 8; i++) {
        int idx = tid + i * 256;
        int k = idx >> 4;
        int cq = idx & 15;
        float4 v = *(const float4*)&W[(size_t)k * 512 + col0 + cq * 4];
        *(float4*)&Bs[k * 64 + cq * 4] = v;
    }
    __syncthreads();

    ull acc2[4][2];
    #pragma unroll
    for (int i = 0; i < 4; i++) { acc2[i][0] = 0ull; acc2[i][1] = 0ull; }

    #pragma unroll 4
    for (int k4 = 0; k4 < 32; k4++) {
        float a_[4][4];
        #pragma unroll
        for (int i = 0; i < 4; i++)
            *(float4*)a_[i] = *(const float4*)&As[(ty * 4 + i) * A_PAD + k4 * 4];
        #pragma unroll
        for (int kk = 0; kk < 4; kk++) {
            const float* bp = &Bs[(k4 * 4 + kk) * 64 + tx * 4];
            ull b01 = *(const ull*)bp;
            ull b23 = *(const ull*)(bp + 2);
            #pragma unroll
            for (int i = 0; i < 4; i++) {
                ull ad = pack2(a_[i][kk], a_[i][kk]);
                ffma2(acc2[i][0], ad, b01);
                ffma2(acc2[i][1], ad, b23);
            }
        }
    }

    // Transpose through SMEM: T[m_local][d_local]
    __syncthreads();
    float* T = smemA;
    #pragma unroll
    for (int i = 0; i < 4; i++) {
        float4 v;
        unpack2(acc2[i][0], v.x, v.y);
        unpack2(acc2[i][1], v.z, v.w);
        *(float4*)&T[(ty * 4 + i) * T_PAD + tx * 4] = v;
    }
    __syncthreads();

    const int b = rowTile >> 9;
    const int n0 = rowTile & 511;
    float* og = g_hpT + (size_t)(b * NH + head) * HD * NA + n0;
    #pragma unroll
    for (int ii = 0; ii < 4; ii++) {
        int f = tid + ii * 256;
        int d = f & 63;
        int mq = f >> 6;
        float4 v;
        v.x = T[(mq * 4 + 0) * T_PAD + d];
        v.y = T[(mq * 4 + 1) * T_PAD + d];
        v.z = T[(mq * 4 + 2) * T_PAD + d];
        v.w = T[(mq * 4 + 3) * T_PAD + d];
        *(float4*)&og[(size_t)d * NA + mq * 4] = v;
    }
}

// ---------------------------------------------------------------------------
// Kernel B: mma.sync tf32 attention.
//   Grid: 2 CTAs per (b,h); each CTA handles 256 n-rows over the full m-scan.
//   SMEM: hpT [64 d][516 pad][m] tf32-rounded; Es/Es02 (this CTA's rows),
//         Ed/Ed02 (all 512 m).
//   Per warp: 32 n-rows = 2 m16 tiles; k-permuted A fragments generated in
//   registers via w = max(Es*Ed, Es02*Ed02); B frags = LDS.64 from hpT;
//   D accumulated in registers; softmax normalizer from register row-sums.
// ---------------------------------------------------------------------------
#define HPT_S 516
#define SM_HPT   0
#define SM_ED    (64 * HPT_S)            // [512]
#define SM_ED02  (SM_ED + 512)           // [512]
#define SM_ES    (SM_ED02 + 512)         // [256]
#define SM_ES02  (SM_ES + 256)           // [256]
#define SM_A     (SM_ES02 + 256)         // [128]
#define SMEM_B_FLOATS (SM_A + 128)
#define SMEM_B_BYTES (SMEM_B_FLOATS * 4)

__device__ __forceinline__ float elu1(float x) {
    return x > 0.f ? x : expm1f(x);
}

__global__ void __launch_bounds__(256, 1) attn_mma_kernel(
    const float* __restrict__ att_a, float* __restrict__ out)
{
    extern __shared__ float sm[];
    float* hpT    = sm + SM_HPT;
    float* Ed_s   = sm + SM_ED;
    float* Ed02_s = sm + SM_ED02;
    float* Es_s   = sm + SM_ES;
    float* Es02_s = sm + SM_ES02;
    float* a_s    = sm + SM_A;

    const int bx = blockIdx.x;
    const int bh = bx >> 1;
    const int head = bh & 7;
    const int nbase = (bx & 1) * 256;
    const int tid = threadIdx.x;
    const int warp = tid >> 5;
    const int lane = tid & 31;
    const int q = lane >> 2;       // group id (rows / B n-col)
    const int c = lane & 3;        // thread-in-group (k position / D col pair)

    if (tid < 128) a_s[tid] = att_a[head * 128 + tid];

    // Stage hpT (tf32-rounded) into padded SMEM
    const float* hg = g_hpT + (size_t)bh * HD * NA;
    #pragma unroll
    for (int i = 0; i < 32; i++) {
        int f = tid + i * 256;           // 8192 float4s
        int d = f >> 7;
        int mq = f & 127;
        float4 v = *(const float4*)&hg[(size_t)d * NA + mq * 4];
        v.x = to_tf32(v.x); v.y = to_tf32(v.y);
        v.z = to_tf32(v.z); v.w = to_tf32(v.w);
        *(float4*)&hpT[d * HPT_S + mq * 4] = v;
    }
    __syncthreads();

    // e-scores from rounded hp: Ed for all m, Es for this CTA's 256 rows.
    for (int m = tid; m < NA; m += 256) {
        float es = 0.f, ed = 0.f;
        #pragma unroll
        for (int d = 0; d < 64; d++) {
            float hp = hpT[d * HPT_S + m];
            es += hp * a_s[d];
            ed += hp * a_s[64 + d];
        }
        Ed_s[m]   = ex2(ed * LOG2E);
        Ed02_s[m] = ex2(ed * (NEG_SLOPE * LOG2E));
        int r = m - nbase;
        if ((unsigned)r < 256u) {
            Es_s[r]   = ex2(es * LOG2E);
            Es02_s[r] = ex2(es * (NEG_SLOPE * LOG2E));
        }
    }
    __syncthreads();

    // Warp owns local rows [warp*32, warp*32+32): two m16 tiles.
    const int r0 = warp * 32 + q;     // tile0 rows r0, r0+8; tile1 rows r0+16, r0+24
    const float EsA0 = Es_s[r0],        EsA1 = Es_s[r0 + 8];
    const float EtA0 = Es02_s[r0],      EtA1 = Es02_s[r0 + 8];
    const float EsB0 = Es_s[r0 + 16],   EsB1 = Es_s[r0 + 24];
    const float EtB0 = Es02_s[r0 + 16], EtB1 = Es02_s[r0 + 24];

    float dA[8][4], dB[8][4];
    #pragma unroll
    for (int t = 0; t < 8; t++)
        #pragma unroll
        for (int j = 0; j < 4; j++) { dA[t][j] = 0.f; dB[t][j] = 0.f; }

    float sA0 = 0.f, sA1 = 0.f, sB0 = 0.f, sB1 = 0.f;
    const float* bbase = hpT + q * HPT_S;

    #pragma unroll 2
    for (int k = 0; k < 64; k++) {
        const int m0 = k * 8 + 2 * c;   // k-permute: phys cols (c, c+4) -> m0, m0+1
        const float2 ed2 = *(const float2*)&Ed_s[m0];
        const float2 et2 = *(const float2*)&Ed02_s[m0];

        // A fragments: w = max(Es*Ed, Es02*Ed02)
        float a0 = fmaxf(EsA0 * ed2.x, EtA0 * et2.x);
        float a1 = fmaxf(EsA1 * ed2.x, EtA1 * et2.x);
        float a2 = fmaxf(EsA0 * ed2.y, EtA0 * et2.y);
        float a3 = fmaxf(EsA1 * ed2.y, EtA1 * et2.y);
        float a4 = fmaxf(EsB0 * ed2.x, EtB0 * et2.x);
        float a5 = fmaxf(EsB1 * ed2.x, EtB1 * et2.x);
        float a6 = fmaxf(EsB0 * ed2.y, EtB0 * et2.y);
        float a7 = fmaxf(EsB1 * ed2.y, EtB1 * et2.y);
        sA0 += a0 + a2; sA1 += a1 + a3;
        sB0 += a4 + a6; sB1 += a5 + a7;

        #pragma unroll
        for (int dt = 0; dt < 8; dt++) {
            const float2 b2 = *(const float2*)&bbase[dt * 8 * HPT_S + m0];
            mma_tf32(dA[dt], a0, a1, a2, a3, b2.x, b2.y);
            mma_tf32(dB[dt], a4, a5, a6, a7, b2.x, b2.y);
        }
    }

    // Full row sums: reduce over the 4 k-lanes (bits 0,1)
    sA0 += __shfl_xor_sync(0xFFFFFFFFu, sA0, 1); sA0 += __shfl_xor_sync(0xFFFFFFFFu, sA0, 2);
    sA1 += __shfl_xor_sync(0xFFFFFFFFu, sA1, 1); sA1 += __shfl_xor_sync(0xFFFFFFFFu, sA1, 2);
    sB0 += __shfl_xor_sync(0xFFFFFFFFu, sB0, 1); sB0 += __shfl_xor_sync(0xFFFFFFFFu, sB0, 2);
    sB1 += __shfl_xor_sync(0xFFFFFFFFu, sB1, 1); sB1 += __shfl_xor_sync(0xFFFFFFFFu, sB1, 2);
    const float ivA0 = 1.f / sA0, ivA1 = 1.f / sA1;
    const float ivB0 = 1.f / sB0, ivB1 = 1.f / sB1;

    // Epilogue: normalize + ELU + store.
    // D frag: c0,c1 -> row gid, cols 2c,2c+1 ; c2,c3 -> row gid+8.
    const size_t orow = ((size_t)bh * NA + nbase + r0) * HD;
    float* o0 = out + orow;                 // row r0
    float* o1 = o0 + 8 * HD;                // row r0+8
    float* o2 = o0 + 16 * HD;               // row r0+16
    float* o3 = o0 + 24 * HD;               // row r0+24
    #pragma unroll
    for (int dt = 0; dt < 8; dt++) {
        const int dc = dt * 8 + 2 * c;
        float2 v;
        v.x = elu1(dA[dt][0] * ivA0); v.y = elu1(dA[dt][1] * ivA0);
        *(float2*)&o0[dc] = v;
        v.x = elu1(dA[dt][2] * ivA1); v.y = elu1(dA[dt][3] * ivA1);
        *(float2*)&o1[dc] = v;
        v.x = elu1(dB[dt][0] * ivB0); v.y = elu1(dB[dt][1] * ivB0);
        *(float2*)&o2[dc] = v;
        v.x = elu1(dB[dt][2] * ivB1); v.y = elu1(dB[dt][3] * ivB1);
        *(float2*)&o3[dc] = v;
    }
}

// ---------------------------------------------------------------------------
extern "C" void kernel_launch(void* const* d_in, const int* in_sizes, int n_in,
                              void* d_out, int out_size)
{
    const float* h     = (const float*)d_in[0];
    const float* W     = (const float*)d_in[1];
    const float* att_a = (const float*)d_in[2];
    float* out = (float*)d_out;

    cudaFuncSetAttribute(gemm_hp_kernel,
        cudaFuncAttributeMaxDynamicSharedMemorySize, SMEM_A_BYTES);
    cudaFuncSetAttribute(attn_mma_kernel,
        cudaFuncAttributeMaxDynamicSharedMemorySize, SMEM_B_BYTES);

    gemm_hp_kernel<<<dim3(NH, (BS * NA) / 64), 256, SMEM_A_BYTES>>>(h, W);
    attn_mma_kernel<<<BS * NH * 2, 256, SMEM_B_BYTES>>>(att_a, out);
}